// round 4
// baseline (speedup 1.0000x reference)
#include <cuda_runtime.h>

// SpatialTransformer: out[b,c,d,h,w] = trilinear_sample(src[b,c], (w,h,d)+flow[b,:,d,h,w])
// align_corners=True normalization cancels; padding_mode='zeros'.
//
// R4: smem-tiled gather. LDG gather is sector-overfetch bound (R1-R3: L1>=95%,
// invariant to load width). Stage a 25x25x17 float2-interleaved src neighborhood
// (halo R=4) in 85KB smem per 16x16x8 output tile; gather via LDS (no sector
// granularity). Rare |flow|>4 samples take an exact global-path fallback.

#define Dz 160
#define Hy 192
#define Wx 160
#define Bn 2
#define HW (Hy * Wx)            // 30720
#define DHW (Dz * Hy * Wx)      // 4915200

#define RH 4                    // halo radius
#define TX 16
#define TY 16
#define TZ 8
#define EX (TX + 2 * RH + 1)    // 25
#define EY (TY + 2 * RH + 1)    // 25
#define EZ (TZ + 2 * RH + 1)    // 17
#define ESZ (EX * EY * EZ)      // 10625
#define SMEM_BYTES (ESZ * (int)sizeof(float2))   // 85000

__global__ __launch_bounds__(256) void warp3d_tiled(
    const float* __restrict__ src,
    const float* __restrict__ flow,
    float* __restrict__ out)
{
    extern __shared__ float2 tile[];

    int bx = blockIdx.x;            // 0..9   (x tiles)
    int by = blockIdx.y;            // 0..11  (y tiles)
    int bzb = blockIdx.z;           // 0..(20*Bn-1)
    int b  = bzb / (Dz / TZ);
    int bz = bzb % (Dz / TZ);

    int x_org = bx * TX - RH;
    int y_org = by * TY - RH;
    int z_org = bz * TZ - RH;

    const float* c0 = src + (size_t)b * 2 * DHW;
    const float* c1 = c0 + DHW;

    // ---- Fill smem tile: interleaved (c0, c1), clamped at volume edges ----
    for (int e = threadIdx.x; e < ESZ; e += 256) {
        int ex = e % EX;
        int et = e / EX;
        int ey = et % EY;
        int ez = et / EY;
        int gx = min(max(x_org + ex, 0), Wx - 1);
        int gy = min(max(y_org + ey, 0), Hy - 1);
        int gz = min(max(z_org + ez, 0), Dz - 1);
        int g = (gz * Hy + gy) * Wx + gx;
        tile[e] = make_float2(__ldg(c0 + g), __ldg(c1 + g));
    }
    __syncthreads();

    // ---- Gather: 256 threads cover 16x16 (x,y), loop over 8 z slices ----
    int tx = threadIdx.x & 15;
    int ty = threadIdx.x >> 4;
    int w = bx * TX + tx;
    int h = by * TY + ty;

    const float* fb = flow + (size_t)b * 3 * DHW;
    float* ob = out + (size_t)b * 2 * DHW;

    #pragma unroll
    for (int kz = 0; kz < TZ; kz++) {
        int d = bz * TZ + kz;
        int s = (d * Hy + h) * Wx + w;

        float x = (float)w + __ldg(fb + s);
        float y = (float)h + __ldg(fb + s + DHW);
        float z = (float)d + __ldg(fb + s + 2 * DHW);

        float x0f = floorf(x), y0f = floorf(y), z0f = floorf(z);
        float fx = x - x0f, fy = y - y0f, fz = z - z0f;
        int x0 = (int)x0f, y0 = (int)y0f, z0 = (int)z0f;
        int x1 = x0 + 1, y1 = y0 + 1, z1 = z0 + 1;

        // Per-axis weights, zeroed when that corner coordinate is outside the volume.
        float wx0 = (x0 >= 0 && x0 < Wx) ? (1.0f - fx) : 0.0f;
        float wx1 = (x1 >= 0 && x1 < Wx) ? fx          : 0.0f;
        float wy0 = (y0 >= 0 && y0 < Hy) ? (1.0f - fy) : 0.0f;
        float wy1 = (y1 >= 0 && y1 < Hy) ? fy          : 0.0f;
        float wz0 = (z0 >= 0 && z0 < Dz) ? (1.0f - fz) : 0.0f;
        float wz1 = (z1 >= 0 && z1 < Dz) ? fz          : 0.0f;

        float w00 = wz0 * wy0, w01 = wz0 * wy1;
        float w10 = wz1 * wy0, w11 = wz1 * wy1;

        int lx = x0 - x_org;
        int ly = y0 - y_org;
        int lz = z0 - z_org;

        float acc0, acc1;
        if (lx >= 0 && lx + 1 < EX &&
            ly >= 0 && ly + 1 < EY &&
            lz >= 0 && lz + 1 < EZ) {
            // In-tile: 8 corners from smem (values at clamped coords; zero
            // weights kill out-of-volume contributions, matching reference).
            const float2* t00 = tile + (lz * EY + ly) * EX + lx;
            const float2* t10 = t00 + EY * EX;
            float2 v000 = t00[0],  v001 = t00[1];
            float2 v010 = t00[EX], v011 = t00[EX + 1];
            float2 v100 = t10[0],  v101 = t10[1];
            float2 v110 = t10[EX], v111 = t10[EX + 1];

            float lo0 = w00 * v000.x + w01 * v010.x + w10 * v100.x + w11 * v110.x;
            float hi0 = w00 * v001.x + w01 * v011.x + w10 * v101.x + w11 * v111.x;
            float lo1 = w00 * v000.y + w01 * v010.y + w10 * v100.y + w11 * v110.y;
            float hi1 = w00 * v001.y + w01 * v011.y + w10 * v101.y + w11 * v111.y;

            acc0 = wx0 * lo0 + wx1 * hi0;
            acc1 = wx0 * lo1 + wx1 * hi1;
        } else {
            // Rare fallback (|flow| > RH): exact global-path gather.
            int x0c = min(max(x0, 0), Wx - 1);
            int x1c = min(max(x1, 0), Wx - 1);
            int y0c = min(max(y0, 0), Hy - 1);
            int y1c = min(max(y1, 0), Hy - 1);
            int z0c = min(max(z0, 0), Dz - 1);
            int z1c = min(max(z1, 0), Dz - 1);

            int zy00 = z0c * HW + y0c * Wx;
            int zy01 = z0c * HW + y1c * Wx;
            int zy10 = z1c * HW + y0c * Wx;
            int zy11 = z1c * HW + y1c * Wx;

            float w000 = w00 * wx0, w001 = w00 * wx1;
            float w010 = w01 * wx0, w011 = w01 * wx1;
            float w100 = w10 * wx0, w101 = w10 * wx1;
            float w110 = w11 * wx0, w111 = w11 * wx1;

            acc0  = w000 * __ldg(c0 + zy00 + x0c) + w001 * __ldg(c0 + zy00 + x1c);
            acc0 += w010 * __ldg(c0 + zy01 + x0c) + w011 * __ldg(c0 + zy01 + x1c);
            acc0 += w100 * __ldg(c0 + zy10 + x0c) + w101 * __ldg(c0 + zy10 + x1c);
            acc0 += w110 * __ldg(c0 + zy11 + x0c) + w111 * __ldg(c0 + zy11 + x1c);

            acc1  = w000 * __ldg(c1 + zy00 + x0c) + w001 * __ldg(c1 + zy00 + x1c);
            acc1 += w010 * __ldg(c1 + zy01 + x0c) + w011 * __ldg(c1 + zy01 + x1c);
            acc1 += w100 * __ldg(c1 + zy10 + x0c) + w101 * __ldg(c1 + zy10 + x1c);
            acc1 += w110 * __ldg(c1 + zy11 + x0c) + w111 * __ldg(c1 + zy11 + x1c);
        }

        ob[s] = acc0;
        ob[DHW + s] = acc1;
    }
}

extern "C" void kernel_launch(void* const* d_in, const int* in_sizes, int n_in,
                              void* d_out, int out_size) {
    const float* src  = (const float*)d_in[0];
    const float* flow = (const float*)d_in[1];
    float* out = (float*)d_out;

    // Opt in to >48KB dynamic smem (idempotent attribute set; not a stream op).
    cudaFuncSetAttribute(warp3d_tiled,
                         cudaFuncAttributeMaxDynamicSharedMemorySize, SMEM_BYTES);

    dim3 grid(Wx / TX, Hy / TY, (Dz / TZ) * Bn);
    warp3d_tiled<<<grid, 256, SMEM_BYTES>>>(src, flow, out);
}

// round 5
// speedup vs baseline: 1.8268x; 1.8268x over previous
#include <cuda_runtime.h>

// SpatialTransformer: out[b,c,d,h,w] = trilinear_sample(src[b,c], (w,h,d)+flow[b,:,d,h,w])
// align_corners=True normalization cancels; padding_mode='zeros'.
//
// R5: smem-tiled gather, fixed for occupancy (R4 failed at occ=24%, alu=41%).
// Tile 32x8x8, halo R=3 -> 39x15x15 float2 = 70.2KB smem, 3 blocks/SM (24 warps).
// Warp-per-row coalesced fill (no div/mod per element). Gather via LDS (no 32B
// sector overfetch, which bound the pure-LDG versions at L1>=95%).
// Samples with |flow|>3 (~0.8%) take the exact global-path fallback.

#define Dz 160
#define Hy 192
#define Wx 160
#define Bn 2
#define HW (Hy * Wx)            // 30720
#define DHW (Dz * Hy * Wx)      // 4915200

#define RH 3                    // halo radius
#define TX 32
#define TY 8
#define TZ 8
#define EX (TX + 2 * RH + 1)    // 39
#define EY (TY + 2 * RH + 1)    // 15
#define EZ (TZ + 2 * RH + 1)    // 15
#define NROWS (EY * EZ)         // 225
#define ESZ (EX * NROWS)        // 8775
#define SMEM_BYTES (ESZ * (int)sizeof(float2))   // 70200

__global__ __launch_bounds__(256, 3) void warp3d_tiled(
    const float* __restrict__ src,
    const float* __restrict__ flow,
    float* __restrict__ out)
{
    extern __shared__ float2 tile[];

    int bx = blockIdx.x;            // 0..4   (x tiles, 160/32)
    int by = blockIdx.y;            // 0..23  (y tiles, 192/8)
    int bzb = blockIdx.z;           // 0..39  (z tiles * batch)
    int b  = bzb / (Dz / TZ);
    int bz = bzb % (Dz / TZ);

    int x_org = bx * TX - RH;
    int y_org = by * TY - RH;
    int z_org = bz * TZ - RH;

    const float* c0 = src + (size_t)b * 2 * DHW;
    const float* c1 = c0 + DHW;

    int lane = threadIdx.x & 31;
    int warp = threadIdx.x >> 5;    // 0..7

    // ---- Fill: each warp copies whole (ez,ey) rows, coalesced strips ----
    for (int r = warp; r < NROWS; r += 8) {
        int ey = r % EY;
        int ez = r / EY;
        int gy = min(max(y_org + ey, 0), Hy - 1);
        int gz = min(max(z_org + ez, 0), Dz - 1);
        const float* r0 = c0 + (gz * Hy + gy) * Wx;
        const float* r1 = c1 + (gz * Hy + gy) * Wx;
        float2* trow = tile + r * EX;

        int gx0 = min(max(x_org + lane, 0), Wx - 1);
        trow[lane] = make_float2(__ldg(r0 + gx0), __ldg(r1 + gx0));
        int ex = lane + 32;
        if (ex < EX) {
            int gx1 = min(max(x_org + ex, 0), Wx - 1);
            trow[ex] = make_float2(__ldg(r0 + gx1), __ldg(r1 + gx1));
        }
    }
    __syncthreads();

    // ---- Gather: lane = x, warp = y, loop over 8 z slices ----
    int w = bx * TX + lane;
    int h = by * TY + warp;

    const float* fb = flow + (size_t)b * 3 * DHW;
    float* ob = out + (size_t)b * 2 * DHW;

    #pragma unroll
    for (int kz = 0; kz < TZ; kz++) {
        int d = bz * TZ + kz;
        int s = (d * Hy + h) * Wx + w;

        float x = (float)w + __ldg(fb + s);
        float y = (float)h + __ldg(fb + s + DHW);
        float z = (float)d + __ldg(fb + s + 2 * DHW);

        float x0f = floorf(x), y0f = floorf(y), z0f = floorf(z);
        float fx = x - x0f, fy = y - y0f, fz = z - z0f;
        int x0 = (int)x0f, y0 = (int)y0f, z0 = (int)z0f;
        int x1 = x0 + 1, y1 = y0 + 1, z1 = z0 + 1;

        // Per-axis weights, zeroed when that corner is outside the volume.
        float wx0 = (x0 >= 0 && x0 < Wx) ? (1.0f - fx) : 0.0f;
        float wx1 = (x1 >= 0 && x1 < Wx) ? fx          : 0.0f;
        float wy0 = (y0 >= 0 && y0 < Hy) ? (1.0f - fy) : 0.0f;
        float wy1 = (y1 >= 0 && y1 < Hy) ? fy          : 0.0f;
        float wz0 = (z0 >= 0 && z0 < Dz) ? (1.0f - fz) : 0.0f;
        float wz1 = (z1 >= 0 && z1 < Dz) ? fz          : 0.0f;

        float w00 = wz0 * wy0, w01 = wz0 * wy1;
        float w10 = wz1 * wy0, w11 = wz1 * wy1;

        int lx = x0 - x_org;
        int ly = y0 - y_org;
        int lz = z0 - z_org;

        float acc0, acc1;
        if (lx >= 0 && lx + 1 < EX &&
            ly >= 0 && ly + 1 < EY &&
            lz >= 0 && lz + 1 < EZ) {
            // In-tile: 8 corners from smem (tile holds clamped values; zero
            // weights kill out-of-volume contributions, matching reference).
            const float2* t00 = tile + (lz * EY + ly) * EX + lx;
            const float2* t10 = t00 + EY * EX;
            float2 v000 = t00[0],  v001 = t00[1];
            float2 v010 = t00[EX], v011 = t00[EX + 1];
            float2 v100 = t10[0],  v101 = t10[1];
            float2 v110 = t10[EX], v111 = t10[EX + 1];

            float lo0 = w00 * v000.x + w01 * v010.x + w10 * v100.x + w11 * v110.x;
            float hi0 = w00 * v001.x + w01 * v011.x + w10 * v101.x + w11 * v111.x;
            float lo1 = w00 * v000.y + w01 * v010.y + w10 * v100.y + w11 * v110.y;
            float hi1 = w00 * v001.y + w01 * v011.y + w10 * v101.y + w11 * v111.y;

            acc0 = wx0 * lo0 + wx1 * hi0;
            acc1 = wx0 * lo1 + wx1 * hi1;
        } else {
            // Rare fallback (|flow| > RH): exact global-path gather.
            int x0c = min(max(x0, 0), Wx - 1);
            int x1c = min(max(x1, 0), Wx - 1);
            int y0c = min(max(y0, 0), Hy - 1);
            int y1c = min(max(y1, 0), Hy - 1);
            int z0c = min(max(z0, 0), Dz - 1);
            int z1c = min(max(z1, 0), Dz - 1);

            int zy00 = z0c * HW + y0c * Wx;
            int zy01 = z0c * HW + y1c * Wx;
            int zy10 = z1c * HW + y0c * Wx;
            int zy11 = z1c * HW + y1c * Wx;

            float w000 = w00 * wx0, w001 = w00 * wx1;
            float w010 = w01 * wx0, w011 = w01 * wx1;
            float w100 = w10 * wx0, w101 = w10 * wx1;
            float w110 = w11 * wx0, w111 = w11 * wx1;

            acc0  = w000 * __ldg(c0 + zy00 + x0c) + w001 * __ldg(c0 + zy00 + x1c);
            acc0 += w010 * __ldg(c0 + zy01 + x0c) + w011 * __ldg(c0 + zy01 + x1c);
            acc0 += w100 * __ldg(c0 + zy10 + x0c) + w101 * __ldg(c0 + zy10 + x1c);
            acc0 += w110 * __ldg(c0 + zy11 + x0c) + w111 * __ldg(c0 + zy11 + x1c);

            acc1  = w000 * __ldg(c1 + zy00 + x0c) + w001 * __ldg(c1 + zy00 + x1c);
            acc1 += w010 * __ldg(c1 + zy01 + x0c) + w011 * __ldg(c1 + zy01 + x1c);
            acc1 += w100 * __ldg(c1 + zy10 + x0c) + w101 * __ldg(c1 + zy10 + x1c);
            acc1 += w110 * __ldg(c1 + zy11 + x0c) + w111 * __ldg(c1 + zy11 + x1c);
        }

        ob[s] = acc0;
        ob[DHW + s] = acc1;
    }
}

extern "C" void kernel_launch(void* const* d_in, const int* in_sizes, int n_in,
                              void* d_out, int out_size) {
    const float* src  = (const float*)d_in[0];
    const float* flow = (const float*)d_in[1];
    float* out = (float*)d_out;

    cudaFuncSetAttribute(warp3d_tiled,
                         cudaFuncAttributeMaxDynamicSharedMemorySize, SMEM_BYTES);

    dim3 grid(Wx / TX, Hy / TY, (Dz / TZ) * Bn);
    warp3d_tiled<<<grid, 256, SMEM_BYTES>>>(src, flow, out);
}

// round 6
// speedup vs baseline: 2.1449x; 1.1741x over previous
#include <cuda_runtime.h>

// SpatialTransformer: out[b,c,d,h,w] = trilinear_sample(src[b,c], (w,h,d)+flow[b,:,d,h,w])
// align_corners=True normalization cancels; padding_mode='zeros'.
//
// R6: smem-tiled gather, occupancy-tuned. R5 showed no saturated pipe at 24
// warps/SM (latency-bound). Tile 32x16x8, halo R=3 -> 39x23x15 float2 = 107.6KB,
// block=512, 2 blocks/SM = 32 warps (47% occ); halo overfetch 3.3x (was 5.0x).
// Gather via LDS (no 32B sector overfetch). |flow|>3 (~0.8%) -> exact global path.

#define Dz 160
#define Hy 192
#define Wx 160
#define Bn 2
#define HW (Hy * Wx)            // 30720
#define DHW (Dz * Hy * Wx)      // 4915200

#define RH 3                    // halo radius
#define TX 32
#define TY 16
#define TZ 8
#define EX (TX + 2 * RH + 1)    // 39
#define EY (TY + 2 * RH + 1)    // 23
#define EZ (TZ + 2 * RH + 1)    // 15
#define NROWS (EY * EZ)         // 345
#define ESZ (EX * NROWS)        // 13455
#define SMEM_BYTES (ESZ * (int)sizeof(float2))   // 107640

#define NTHREADS 512
#define NWARPS (NTHREADS / 32)  // 16

__global__ __launch_bounds__(NTHREADS, 2) void warp3d_tiled(
    const float* __restrict__ src,
    const float* __restrict__ flow,
    float* __restrict__ out)
{
    extern __shared__ float2 tile[];

    int bx = blockIdx.x;            // 0..4   (x tiles, 160/32)
    int by = blockIdx.y;            // 0..11  (y tiles, 192/16)
    int bzb = blockIdx.z;           // 0..39  (z tiles * batch)
    int b  = bzb / (Dz / TZ);
    int bz = bzb % (Dz / TZ);

    int x_org = bx * TX - RH;
    int y_org = by * TY - RH;
    int z_org = bz * TZ - RH;

    const float* c0 = src + (size_t)b * 2 * DHW;
    const float* c1 = c0 + DHW;

    int lane = threadIdx.x & 31;
    int warp = threadIdx.x >> 5;    // 0..15

    // ---- Fill: each warp copies whole (ez,ey) rows, coalesced strips ----
    for (int r = warp; r < NROWS; r += NWARPS) {
        int ey = r % EY;
        int ez = r / EY;
        int gy = min(max(y_org + ey, 0), Hy - 1);
        int gz = min(max(z_org + ez, 0), Dz - 1);
        const float* r0 = c0 + (gz * Hy + gy) * Wx;
        const float* r1 = c1 + (gz * Hy + gy) * Wx;
        float2* trow = tile + r * EX;

        int gx0 = min(max(x_org + lane, 0), Wx - 1);
        trow[lane] = make_float2(__ldg(r0 + gx0), __ldg(r1 + gx0));
        int ex = lane + 32;
        if (ex < EX) {
            int gx1 = min(max(x_org + ex, 0), Wx - 1);
            trow[ex] = make_float2(__ldg(r0 + gx1), __ldg(r1 + gx1));
        }
    }
    __syncthreads();

    // ---- Gather: lane = x, warp = y (16 warps), loop over 8 z slices ----
    int w = bx * TX + lane;
    int h = by * TY + warp;

    const float* fb = flow + (size_t)b * 3 * DHW;
    float* ob = out + (size_t)b * 2 * DHW;

    int s_base = ((bz * TZ) * Hy + h) * Wx + w;

    #pragma unroll
    for (int kz = 0; kz < TZ; kz++) {
        int d = bz * TZ + kz;
        int s = s_base + kz * HW;

        float x = (float)w + __ldg(fb + s);
        float y = (float)h + __ldg(fb + s + DHW);
        float z = (float)d + __ldg(fb + s + 2 * DHW);

        float x0f = floorf(x), y0f = floorf(y), z0f = floorf(z);
        float fx = x - x0f, fy = y - y0f, fz = z - z0f;
        int x0 = (int)x0f, y0 = (int)y0f, z0 = (int)z0f;
        int x1 = x0 + 1, y1 = y0 + 1, z1 = z0 + 1;

        // Per-axis weights, zeroed when that corner is outside the volume.
        float wx0 = (x0 >= 0 && x0 < Wx) ? (1.0f - fx) : 0.0f;
        float wx1 = (x1 >= 0 && x1 < Wx) ? fx          : 0.0f;
        float wy0 = (y0 >= 0 && y0 < Hy) ? (1.0f - fy) : 0.0f;
        float wy1 = (y1 >= 0 && y1 < Hy) ? fy          : 0.0f;
        float wz0 = (z0 >= 0 && z0 < Dz) ? (1.0f - fz) : 0.0f;
        float wz1 = (z1 >= 0 && z1 < Dz) ? fz          : 0.0f;

        float w00 = wz0 * wy0, w01 = wz0 * wy1;
        float w10 = wz1 * wy0, w11 = wz1 * wy1;

        int lx = x0 - x_org;
        int ly = y0 - y_org;
        int lz = z0 - z_org;

        float acc0, acc1;
        if (lx >= 0 && lx + 1 < EX &&
            ly >= 0 && ly + 1 < EY &&
            lz >= 0 && lz + 1 < EZ) {
            // In-tile: 8 corners from smem (tile holds clamped values; zero
            // weights kill out-of-volume contributions, matching reference).
            const float2* t00 = tile + (lz * EY + ly) * EX + lx;
            const float2* t10 = t00 + EY * EX;
            float2 v000 = t00[0],  v001 = t00[1];
            float2 v010 = t00[EX], v011 = t00[EX + 1];
            float2 v100 = t10[0],  v101 = t10[1];
            float2 v110 = t10[EX], v111 = t10[EX + 1];

            float lo0 = w00 * v000.x + w01 * v010.x + w10 * v100.x + w11 * v110.x;
            float hi0 = w00 * v001.x + w01 * v011.x + w10 * v101.x + w11 * v111.x;
            float lo1 = w00 * v000.y + w01 * v010.y + w10 * v100.y + w11 * v110.y;
            float hi1 = w00 * v001.y + w01 * v011.y + w10 * v101.y + w11 * v111.y;

            acc0 = wx0 * lo0 + wx1 * hi0;
            acc1 = wx0 * lo1 + wx1 * hi1;
        } else {
            // Rare fallback (|flow| > RH): exact global-path gather.
            int x0c = min(max(x0, 0), Wx - 1);
            int x1c = min(max(x1, 0), Wx - 1);
            int y0c = min(max(y0, 0), Hy - 1);
            int y1c = min(max(y1, 0), Hy - 1);
            int z0c = min(max(z0, 0), Dz - 1);
            int z1c = min(max(z1, 0), Dz - 1);

            int zy00 = z0c * HW + y0c * Wx;
            int zy01 = z0c * HW + y1c * Wx;
            int zy10 = z1c * HW + y0c * Wx;
            int zy11 = z1c * HW + y1c * Wx;

            float w000 = w00 * wx0, w001 = w00 * wx1;
            float w010 = w01 * wx0, w011 = w01 * wx1;
            float w100 = w10 * wx0, w101 = w10 * wx1;
            float w110 = w11 * wx0, w111 = w11 * wx1;

            acc0  = w000 * __ldg(c0 + zy00 + x0c) + w001 * __ldg(c0 + zy00 + x1c);
            acc0 += w010 * __ldg(c0 + zy01 + x0c) + w011 * __ldg(c0 + zy01 + x1c);
            acc0 += w100 * __ldg(c0 + zy10 + x0c) + w101 * __ldg(c0 + zy10 + x1c);
            acc0 += w110 * __ldg(c0 + zy11 + x0c) + w111 * __ldg(c0 + zy11 + x1c);

            acc1  = w000 * __ldg(c1 + zy00 + x0c) + w001 * __ldg(c1 + zy00 + x1c);
            acc1 += w010 * __ldg(c1 + zy01 + x0c) + w011 * __ldg(c1 + zy01 + x1c);
            acc1 += w100 * __ldg(c1 + zy10 + x0c) + w101 * __ldg(c1 + zy10 + x1c);
            acc1 += w110 * __ldg(c1 + zy11 + x0c) + w111 * __ldg(c1 + zy11 + x1c);
        }

        ob[s] = acc0;
        ob[DHW + s] = acc1;
    }
}

extern "C" void kernel_launch(void* const* d_in, const int* in_sizes, int n_in,
                              void* d_out, int out_size) {
    const float* src  = (const float*)d_in[0];
    const float* flow = (const float*)d_in[1];
    float* out = (float*)d_out;

    cudaFuncSetAttribute(warp3d_tiled,
                         cudaFuncAttributeMaxDynamicSharedMemorySize, SMEM_BYTES);

    dim3 grid(Wx / TX, Hy / TY, (Dz / TZ) * Bn);
    warp3d_tiled<<<grid, NTHREADS, SMEM_BYTES>>>(src, flow, out);
}